// round 6
// baseline (speedup 1.0000x reference)
#include <cuda_runtime.h>
#include <cuda_bf16.h>
#include <cstdint>

// Problem constants
#define BB 2
#define TT 4096
#define CC 768
#define HH 12
#define HS 64
#define MM (BB*TT)          // 8192
#define KKC 768
#define SCALE_F 0.125f      // HS^-0.5

// ---------------------------------------------------------------------------
// Scratch (allocation-free: __device__ globals) — all bf16 hi/lo pairs
// ---------------------------------------------------------------------------
__device__ __nv_bfloat16 g_Qh[BB*HH*TT*HS], g_Ql[BB*HH*TT*HS];   // scaled Q
__device__ __nv_bfloat16 g_Kh[BB*HH*TT*HS], g_Kl[BB*HH*TT*HS];
__device__ __nv_bfloat16 g_Vh[BB*HH*TT*HS], g_Vl[BB*HH*TT*HS];
__device__ __nv_bfloat16 g_xh[MM*CC],    g_xl[MM*CC];
__device__ __nv_bfloat16 g_wah[3*CC*CC], g_wal[3*CC*CC];
__device__ __nv_bfloat16 g_wph[CC*CC],   g_wpl[CC*CC];
__device__ __nv_bfloat16 g_ah[MM*CC],    g_al[MM*CC];            // attn out

// ---------------------------------------------------------------------------
// Helpers
// ---------------------------------------------------------------------------
__device__ __forceinline__ uint32_t smem_u32(const void* p) {
    uint32_t r;
    asm("{ .reg .u64 t; cvta.to.shared.u64 t, %1; cvt.u32.u64 %0, t; }" : "=r"(r) : "l"(p));
    return r;
}
__device__ __forceinline__ void mma16816(float c[4], const uint32_t a[4], const uint32_t b0, const uint32_t b1) {
    asm volatile("mma.sync.aligned.m16n8k16.row.col.f32.bf16.bf16.f32 "
                 "{%0,%1,%2,%3}, {%4,%5,%6,%7}, {%8,%9}, {%0,%1,%2,%3};"
                 : "+f"(c[0]), "+f"(c[1]), "+f"(c[2]), "+f"(c[3])
                 : "r"(a[0]), "r"(a[1]), "r"(a[2]), "r"(a[3]), "r"(b0), "r"(b1));
}
__device__ __forceinline__ void ldsm_x4(uint32_t r[4], uint32_t addr) {
    asm volatile("ldmatrix.sync.aligned.m8n8.x4.shared.b16 {%0,%1,%2,%3}, [%4];"
                 : "=r"(r[0]), "=r"(r[1]), "=r"(r[2]), "=r"(r[3]) : "r"(addr));
}
__device__ __forceinline__ void ldsm_x4t(uint32_t r[4], uint32_t addr) {
    asm volatile("ldmatrix.sync.aligned.m8n8.x4.trans.shared.b16 {%0,%1,%2,%3}, [%4];"
                 : "=r"(r[0]), "=r"(r[1]), "=r"(r[2]), "=r"(r[3]) : "r"(addr));
}
__device__ __forceinline__ void cp16(uint32_t smem, const void* g) {
    asm volatile("cp.async.cg.shared.global [%0], [%1], 16;" :: "r"(smem), "l"(g));
}
#define CP_COMMIT() asm volatile("cp.async.commit_group;" ::: "memory")
#define CP_WAIT1()  asm volatile("cp.async.wait_group 1;" ::: "memory")
#define CP_WAIT0()  asm volatile("cp.async.wait_group 0;" ::: "memory")

__device__ __forceinline__ uint32_t pack_bf2(__nv_bfloat16 lo, __nv_bfloat16 hi) {
    return ((uint32_t)__bfloat16_as_ushort(hi) << 16) | (uint32_t)__bfloat16_as_ushort(lo);
}
__device__ __forceinline__ void pack_split(float a, float b, uint32_t& h, uint32_t& l) {
    __nv_bfloat16 ha = __float2bfloat16(a), hb = __float2bfloat16(b);
    __nv_bfloat16 la = __float2bfloat16(a - __bfloat162float(ha));
    __nv_bfloat16 lb = __float2bfloat16(b - __bfloat162float(hb));
    h = pack_bf2(ha, hb);
    l = pack_bf2(la, lb);
}

// ---------------------------------------------------------------------------
// Split fp32 -> bf16 hi + lo (inputs only)
// ---------------------------------------------------------------------------
__global__ __launch_bounds__(256) void split_kernel(
    const float* __restrict__ in, __nv_bfloat16* __restrict__ hi,
    __nv_bfloat16* __restrict__ lo, int n)
{
    int i = (blockIdx.x * 256 + threadIdx.x) * 4;
    if (i >= n) return;
    float4 v = *(const float4*)(in + i);
    uint2 hv, lv;
    pack_split(v.x, v.y, hv.x, lv.x);
    pack_split(v.z, v.w, hv.y, lv.y);
    *(uint2*)(hi + i) = hv;
    *(uint2*)(lo + i) = lv;
}

// ---------------------------------------------------------------------------
// Dense GEMM via mma.sync, cp.async double-buffered. 128x128 tile, BK=32.
// MMAs interleaved across 4 accumulators to break RAW chains.
// ---------------------------------------------------------------------------
#define GPAD 40
#define G_ARR (128*GPAD)
#define G_STAGE (4*G_ARR)
#define GEMM_SMEM (2*G_STAGE*2)

template<int MODE>
__global__ __launch_bounds__(256) void mma_gemm(
    const __nv_bfloat16* __restrict__ Ah, const __nv_bfloat16* __restrict__ Al,
    const __nv_bfloat16* __restrict__ Bh, const __nv_bfloat16* __restrict__ Bl,
    const float* __restrict__ bias, float* __restrict__ Cout, int N)
{
    extern __shared__ __nv_bfloat16 smp[];
    const uint32_t sm_base = smem_u32(smp);

    const int tid  = threadIdx.x;
    const int lane = tid & 31;
    const int wid  = tid >> 5;
    const int wm   = wid & 3;
    const int wn   = wid >> 2;
    const int row0 = blockIdx.y * 128;
    const int col0 = blockIdx.x * 128;
    const int grp  = lane >> 2, qp = lane & 3;

    float acc[2][8][4];
#pragma unroll
    for (int mt = 0; mt < 2; mt++)
#pragma unroll
        for (int j = 0; j < 8; j++)
#pragma unroll
            for (int c = 0; c < 4; c++) acc[mt][j][c] = 0.f;

    const int arow_off = ((lane >> 3) & 1) * 8 + (lane & 7);
    const int acol_off = (lane >> 4) * 8;
    const int b4row = wn * 64 + ((lane >> 4) & 1) * 8 + (lane & 7);
    const int b4col = ((lane >> 3) & 1) * 8;

    auto fill = [&](int buf, int kt) {
        const uint32_t d0 = sm_base + buf * G_STAGE * 2;
#pragma unroll
        for (int u = 0; u < 8; u++) {
            const int idx = tid + u * 256;
            const int arr = idx >> 9;
            const int w   = idx & 511;
            const int r   = w >> 2;
            const int c8  = (w & 3) * 8;
            const __nv_bfloat16* src =
                (arr == 0) ? Ah + (size_t)(row0 + r) * KKC + kt + c8 :
                (arr == 1) ? Al + (size_t)(row0 + r) * KKC + kt + c8 :
                (arr == 2) ? Bh + (size_t)(col0 + r) * KKC + kt + c8 :
                             Bl + (size_t)(col0 + r) * KKC + kt + c8;
            cp16(d0 + (arr * G_ARR + r * GPAD + c8) * 2, src);
        }
        CP_COMMIT();
    };

    fill(0, 0);
    const int NIT = KKC / 32;
    for (int it = 0; it < NIT; it++) {
        const int buf = it & 1;
        if (it + 1 < NIT) { fill(buf ^ 1, (it + 1) * 32); CP_WAIT1(); }
        else               CP_WAIT0();
        __syncthreads();

        const uint32_t sAh = sm_base + (buf * G_STAGE) * 2;
        const uint32_t sAl = sAh + G_ARR * 2;
        const uint32_t sBh = sAh + 2 * G_ARR * 2;
        const uint32_t sBl = sAh + 3 * G_ARR * 2;

#pragma unroll
        for (int ks = 0; ks < 2; ks++) {
            uint32_t afh[2][4], afl[2][4];
#pragma unroll
            for (int mt = 0; mt < 2; mt++) {
                const int aoff = ((wm * 32 + mt * 16 + arow_off) * GPAD + ks * 16 + acol_off) * 2;
                ldsm_x4(afh[mt], sAh + aoff);
                ldsm_x4(afl[mt], sAl + aoff);
            }
#pragma unroll
            for (int jp = 0; jp < 4; jp++) {
                uint32_t bh4[4], bl4[4];
                const int boff = ((b4row + jp * 16) * GPAD + ks * 16 + b4col) * 2;
                ldsm_x4(bh4, sBh + boff);
                ldsm_x4(bl4, sBl + boff);
                // pass hh over 4 accs, then hl, then lh (chain distance 4)
                mma16816(acc[0][2*jp],   afh[0], bh4[0], bh4[1]);
                mma16816(acc[1][2*jp],   afh[1], bh4[0], bh4[1]);
                mma16816(acc[0][2*jp+1], afh[0], bh4[2], bh4[3]);
                mma16816(acc[1][2*jp+1], afh[1], bh4[2], bh4[3]);
                mma16816(acc[0][2*jp],   afh[0], bl4[0], bl4[1]);
                mma16816(acc[1][2*jp],   afh[1], bl4[0], bl4[1]);
                mma16816(acc[0][2*jp+1], afh[0], bl4[2], bl4[3]);
                mma16816(acc[1][2*jp+1], afh[1], bl4[2], bl4[3]);
                mma16816(acc[0][2*jp],   afl[0], bh4[0], bh4[1]);
                mma16816(acc[1][2*jp],   afl[1], bh4[0], bh4[1]);
                mma16816(acc[0][2*jp+1], afl[0], bh4[2], bh4[3]);
                mma16816(acc[1][2*jp+1], afl[1], bh4[2], bh4[3]);
            }
        }
        __syncthreads();
    }

    // Epilogue
#pragma unroll
    for (int mt = 0; mt < 2; mt++) {
#pragma unroll
        for (int j = 0; j < 8; j++) {
            const int n = col0 + wn * 64 + j * 8 + qp * 2;
            const float b0 = bias[n], b1 = bias[n + 1];
#pragma unroll
            for (int rr = 0; rr < 2; rr++) {
                const int m = row0 + wm * 32 + mt * 16 + grp + rr * 8;
                float v0 = acc[mt][j][rr * 2 + 0] + b0;
                float v1 = acc[mt][j][rr * 2 + 1] + b1;
                if (MODE == 0) {
                    const int which = n / CC;
                    const int rm = n % CC;
                    const int h = rm / HS, e = rm % HS;
                    const int bb = m / TT, t = m % TT;
                    const size_t idx = ((size_t)(bb * HH + h) * TT + t) * HS + e;
                    uint32_t hw, lw;
                    if (which == 0) {
                        pack_split(v0 * SCALE_F, v1 * SCALE_F, hw, lw);
                        *(uint32_t*)&g_Qh[idx] = hw; *(uint32_t*)&g_Ql[idx] = lw;
                    } else if (which == 1) {
                        pack_split(v0, v1, hw, lw);
                        *(uint32_t*)&g_Kh[idx] = hw; *(uint32_t*)&g_Kl[idx] = lw;
                    } else {
                        pack_split(v0, v1, hw, lw);
                        *(uint32_t*)&g_Vh[idx] = hw; *(uint32_t*)&g_Vl[idx] = lw;
                    }
                } else {
                    float* p = Cout + (size_t)m * N + n;
                    *(float2*)p = make_float2(v0, v1);
                }
            }
        }
    }
}

// ---------------------------------------------------------------------------
// Flash attention. 1-D grid (768), LPT schedule. 8 warps x 16 q rows; Bc=64.
// MMAs interleaved across 4 accumulators to break RAW chains.
// ---------------------------------------------------------------------------
#define APAD 72
#define A_ARR (64*APAD)
#define A_STAGE (4*A_ARR)
#define QFRAG_B (8*4*8*32*4)
#define ATTN_SMEM (2*A_STAGE*2 + QFRAG_B)

__global__ __launch_bounds__(256, 2) void attn_mma()
{
    extern __shared__ __nv_bfloat16 smp[];
    const uint32_t sm_base = smem_u32(smp);
    uint32_t* qsm = (uint32_t*)((char*)smp + 2 * A_STAGE * 2);

    const int tid  = threadIdx.x;
    const int lane = tid & 31;
    const int wid  = tid >> 5;
    const int qi   = (TT/128 - 1) - (blockIdx.x / (BB*HH));
    const int bh   = blockIdx.x % (BB*HH);
    const int q0   = qi * 128;
    const int grp  = lane >> 2, qp = lane & 3;
    const int wr0  = q0 + wid * 16;

    const size_t bh_base = (size_t)bh * TT * HS;

    // Build Q fragments once -> per-warp SMEM
    {
#pragma unroll
        for (int ks = 0; ks < 4; ks++) {
            const int c0 = ks * 16 + qp * 2;
            const size_t r0 = bh_base + (size_t)(wr0 + grp) * HS;
            const size_t r1 = r0 + 8 * HS;
            uint32_t* q0p = &qsm[((wid * 4 + ks) * 8) * 32 + lane];
            q0p[0*32] = *(const uint32_t*)&g_Qh[r0 + c0];
            q0p[1*32] = *(const uint32_t*)&g_Qh[r1 + c0];
            q0p[2*32] = *(const uint32_t*)&g_Qh[r0 + c0 + 8];
            q0p[3*32] = *(const uint32_t*)&g_Qh[r1 + c0 + 8];
            q0p[4*32] = *(const uint32_t*)&g_Ql[r0 + c0];
            q0p[5*32] = *(const uint32_t*)&g_Ql[r1 + c0];
            q0p[6*32] = *(const uint32_t*)&g_Ql[r0 + c0 + 8];
            q0p[7*32] = *(const uint32_t*)&g_Ql[r1 + c0 + 8];
        }
    }

    float oacc[8][4];
    float mi[2] = {-1e30f, -1e30f}, li[2] = {0.f, 0.f};
#pragma unroll
    for (int j = 0; j < 8; j++)
#pragma unroll
        for (int c = 0; c < 4; c++) oacc[j][c] = 0.f;

    const int k4row = ((lane >> 4) & 1) * 8 + (lane & 7);
    const int k4col = ((lane >> 3) & 1) * 8;
    const int v4row = ((lane >> 3) & 1) * 8 + (lane & 7);
    const int v4col = ((lane >> 4) & 1) * 8;

    auto fillkv = [&](int buf, int k0) {
        const uint32_t d0 = sm_base + buf * A_STAGE * 2;
        const size_t gb = bh_base + (size_t)k0 * HS;
#pragma unroll
        for (int u = 0; u < 8; u++) {
            const int idx = tid + u * 256;
            const int arr = idx >> 9;
            const int w   = idx & 511;
            const int r   = w >> 3;
            const int c8  = (w & 7) * 8;
            const __nv_bfloat16* src =
                (arr == 0) ? g_Kh + gb + (size_t)r * HS + c8 :
                (arr == 1) ? g_Kl + gb + (size_t)r * HS + c8 :
                (arr == 2) ? g_Vh + gb + (size_t)r * HS + c8 :
                             g_Vl + gb + (size_t)r * HS + c8;
            cp16(d0 + (arr * A_ARR + r * APAD + c8) * 2, src);
        }
        CP_COMMIT();
    };

    const int niters = 2 * qi + 2;
    fillkv(0, 0);
    for (int kj = 0; kj < niters; kj++) {
        const int k0 = kj * 64;
        const int buf = kj & 1;
        if (kj + 1 < niters) { fillkv(buf ^ 1, (kj + 1) * 64); CP_WAIT1(); }
        else                   CP_WAIT0();
        __syncthreads();

        if (k0 <= wr0 + 15) {
            const uint32_t sKh = sm_base + (buf * A_STAGE) * 2;
            const uint32_t sKl = sKh + A_ARR * 2;
            const uint32_t sVh = sKh + 2 * A_ARR * 2;
            const uint32_t sVl = sKh + 3 * A_ARR * 2;

            // S = Q K^T, jp unrolled x2 -> 4 interleaved accumulators
            float sacc[8][4];
#pragma unroll
            for (int j = 0; j < 8; j++)
#pragma unroll
                for (int c = 0; c < 4; c++) sacc[j][c] = 0.f;

#pragma unroll
            for (int ks = 0; ks < 4; ks++) {
                uint32_t qfh[4], qfl[4];
                const uint32_t* qp0 = &qsm[((wid * 4 + ks) * 8) * 32 + lane];
#pragma unroll
                for (int r = 0; r < 4; r++) { qfh[r] = qp0[r*32]; qfl[r] = qp0[(r+4)*32]; }
#pragma unroll
                for (int jp2 = 0; jp2 < 2; jp2++) {
                    uint32_t kha[4], kla[4], khb[4], klb[4];
                    const int offa = (((2*jp2)   * 16 + k4row) * APAD + ks * 16 + k4col) * 2;
                    const int offb = (((2*jp2+1) * 16 + k4row) * APAD + ks * 16 + k4col) * 2;
                    ldsm_x4(kha, sKh + offa);
                    ldsm_x4(kla, sKl + offa);
                    ldsm_x4(khb, sKh + offb);
                    ldsm_x4(klb, sKl + offb);
                    float* a0 = sacc[4*jp2];   float* a1 = sacc[4*jp2+1];
                    float* a2 = sacc[4*jp2+2]; float* a3 = sacc[4*jp2+3];
                    mma16816(a0, qfh, kha[0], kha[1]);
                    mma16816(a1, qfh, kha[2], kha[3]);
                    mma16816(a2, qfh, khb[0], khb[1]);
                    mma16816(a3, qfh, khb[2], khb[3]);
                    mma16816(a0, qfh, kla[0], kla[1]);
                    mma16816(a1, qfh, kla[2], kla[3]);
                    mma16816(a2, qfh, klb[0], klb[1]);
                    mma16816(a3, qfh, klb[2], klb[3]);
                    mma16816(a0, qfl, kha[0], kha[1]);
                    mma16816(a1, qfl, kha[2], kha[3]);
                    mma16816(a2, qfl, khb[0], khb[1]);
                    mma16816(a3, qfl, khb[2], khb[3]);
                }
            }

            // Causal mask (partially-masked tiles only)
            if (k0 + 63 > wr0) {
#pragma unroll
                for (int j = 0; j < 8; j++) {
#pragma unroll
                    for (int c = 0; c < 4; c++) {
                        const int col = k0 + j * 8 + qp * 2 + (c & 1);
                        const int row = wr0 + grp + ((c >> 1) * 8);
                        if (col > row) sacc[j][c] = -1e30f;
                    }
                }
            }

            // Online softmax
#pragma unroll
            for (int rr = 0; rr < 2; rr++) {
                float mx = -1e30f;
#pragma unroll
                for (int j = 0; j < 8; j++) {
                    mx = fmaxf(mx, sacc[j][rr * 2]);
                    mx = fmaxf(mx, sacc[j][rr * 2 + 1]);
                }
                mx = fmaxf(mx, __shfl_xor_sync(0xffffffffu, mx, 1));
                mx = fmaxf(mx, __shfl_xor_sync(0xffffffffu, mx, 2));
                const float mnew = fmaxf(mi[rr], mx);
                const float corr = __expf(mi[rr] - mnew);
                float sum = 0.f;
#pragma unroll
                for (int j = 0; j < 8; j++) {
                    float p0 = __expf(sacc[j][rr * 2]     - mnew);
                    float p1 = __expf(sacc[j][rr * 2 + 1] - mnew);
                    sacc[j][rr * 2] = p0; sacc[j][rr * 2 + 1] = p1;
                    sum += p0 + p1;
                }
                sum += __shfl_xor_sync(0xffffffffu, sum, 1);
                sum += __shfl_xor_sync(0xffffffffu, sum, 2);
                li[rr] = li[rr] * corr + sum;
                mi[rr] = mnew;
#pragma unroll
                for (int j = 0; j < 8; j++) {
                    oacc[j][rr * 2]     *= corr;
                    oacc[j][rr * 2 + 1] *= corr;
                }
            }

            // P fragments in-register
            uint32_t ph[4][4], pl[4][4];
#pragma unroll
            for (int ks = 0; ks < 4; ks++) {
                const int j0 = 2 * ks, j1 = 2 * ks + 1;
                pack_split(sacc[j0][0], sacc[j0][1], ph[ks][0], pl[ks][0]);
                pack_split(sacc[j0][2], sacc[j0][3], ph[ks][1], pl[ks][1]);
                pack_split(sacc[j1][0], sacc[j1][1], ph[ks][2], pl[ks][2]);
                pack_split(sacc[j1][2], sacc[j1][3], ph[ks][3], pl[ks][3]);
            }

            // O += P V, jop unrolled x2 -> 4 interleaved accumulators
#pragma unroll
            for (int ks = 0; ks < 4; ks++) {
#pragma unroll
                for (int jq = 0; jq < 2; jq++) {
                    uint32_t vha[4], vla[4], vhb[4], vlb[4];
                    const int offa = ((ks * 16 + v4row) * APAD + (4*jq)   * 8 + v4col) * 2;
                    const int offb = ((ks * 16 + v4row) * APAD + (4*jq+2) * 8 + v4col) * 2;
                    ldsm_x4t(vha, sVh + offa);
                    ldsm_x4t(vla, sVl + offa);
                    ldsm_x4t(vhb, sVh + offb);
                    ldsm_x4t(vlb, sVl + offb);
                    float* o0 = oacc[4*jq];   float* o1 = oacc[4*jq+1];
                    float* o2 = oacc[4*jq+2]; float* o3 = oacc[4*jq+3];
                    mma16816(o0, ph[ks], vha[0], vha[1]);
                    mma16816(o1, ph[ks], vha[2], vha[3]);
                    mma16816(o2, ph[ks], vhb[0], vhb[1]);
                    mma16816(o3, ph[ks], vhb[2], vhb[3]);
                    mma16816(o0, ph[ks], vla[0], vla[1]);
                    mma16816(o1, ph[ks], vla[2], vla[3]);
                    mma16816(o2, ph[ks], vlb[0], vlb[1]);
                    mma16816(o3, ph[ks], vlb[2], vlb[3]);
                    mma16816(o0, pl[ks], vha[0], vha[1]);
                    mma16816(o1, pl[ks], vha[2], vha[3]);
                    mma16816(o2, pl[ks], vhb[0], vhb[1]);
                    mma16816(o3, pl[ks], vhb[2], vhb[3]);
                }
            }
        }
        __syncthreads();
    }

    // Epilogue: write bf16 hi/lo of O directly
    const int b = bh / HH, h = bh % HH;
#pragma unroll
    for (int rr = 0; rr < 2; rr++) {
        const int t = wr0 + grp + rr * 8;
        const float inv = 1.f / li[rr];
        const size_t base = (size_t)(b * TT + t) * CC + h * HS;
#pragma unroll
        for (int jo = 0; jo < 8; jo++) {
            uint32_t hw, lw;
            pack_split(oacc[jo][rr * 2] * inv, oacc[jo][rr * 2 + 1] * inv, hw, lw);
            const size_t off = base + jo * 8 + qp * 2;
            *(uint32_t*)&g_ah[off] = hw;
            *(uint32_t*)&g_al[off] = lw;
        }
    }
}

// ---------------------------------------------------------------------------
extern "C" void kernel_launch(void* const* d_in, const int* in_sizes, int n_in,
                              void* d_out, int out_size)
{
    const float* x      = (const float*)d_in[0];
    const float* w_attn = (const float*)d_in[1];
    const float* b_attn = (const float*)d_in[2];
    const float* w_proj = (const float*)d_in[3];
    const float* b_proj = (const float*)d_in[4];
    float* out = (float*)d_out;
    (void)in_sizes; (void)n_in; (void)out_size;

    __nv_bfloat16 *xh, *xl, *wah, *wal, *wph, *wpl, *ah, *al;
    cudaGetSymbolAddress((void**)&xh,  g_xh);  cudaGetSymbolAddress((void**)&xl,  g_xl);
    cudaGetSymbolAddress((void**)&wah, g_wah); cudaGetSymbolAddress((void**)&wal, g_wal);
    cudaGetSymbolAddress((void**)&wph, g_wph); cudaGetSymbolAddress((void**)&wpl, g_wpl);
    cudaGetSymbolAddress((void**)&ah,  g_ah);  cudaGetSymbolAddress((void**)&al,  g_al);

    cudaFuncSetAttribute(mma_gemm<0>, cudaFuncAttributeMaxDynamicSharedMemorySize, GEMM_SMEM);
    cudaFuncSetAttribute(mma_gemm<1>, cudaFuncAttributeMaxDynamicSharedMemorySize, GEMM_SMEM);
    cudaFuncSetAttribute(attn_mma,    cudaFuncAttributeMaxDynamicSharedMemorySize, ATTN_SMEM);

    // 0) split inputs
    split_kernel<<<(MM*CC/4 + 255)/256, 256>>>(x, xh, xl, MM*CC);
    split_kernel<<<(3*CC*CC/4 + 255)/256, 256>>>(w_attn, wah, wal, 3*CC*CC);
    split_kernel<<<(CC*CC/4 + 255)/256, 256>>>(w_proj, wph, wpl, CC*CC);

    // 1) QKV projection -> pre-split, pre-scaled Q/K/V (bf16 hi/lo)
    mma_gemm<0><<<dim3(3*CC/128, MM/128), 256, GEMM_SMEM>>>(xh, xl, wah, wal, b_attn, nullptr, 3*CC);

    // 2) Flash attention (LPT 1-D grid)
    attn_mma<<<(TT/128) * BB * HH, 256, ATTN_SMEM>>>();

    // 3) Output projection
    mma_gemm<1><<<dim3(CC/128, MM/128), 256, GEMM_SMEM>>>(ah, al, wph, wpl, b_proj, out, CC);
}

// round 7
// speedup vs baseline: 1.3154x; 1.3154x over previous
#include <cuda_runtime.h>
#include <cuda_bf16.h>
#include <cuda_fp16.h>
#include <cstdint>

// Problem constants
#define BB 2
#define TT 4096
#define CC 768
#define HH 12
#define HS 64
#define MM (BB*TT)          // 8192
#define KKC 768
#define SCALE_F 0.125f      // HS^-0.5

// ---------------------------------------------------------------------------
// Scratch (allocation-free: __device__ globals)
// ---------------------------------------------------------------------------
__device__ __nv_bfloat16 g_Qh[BB*HH*TT*HS], g_Ql[BB*HH*TT*HS];   // scaled Q (hi/lo)
__device__ __nv_bfloat16 g_Kh[BB*HH*TT*HS], g_Kl[BB*HH*TT*HS];
__device__ __nv_bfloat16 g_Vh[BB*HH*TT*HS], g_Vl[BB*HH*TT*HS];
__device__ __half g_x16[MM*CC];          // fp16 single-precision GEMM operands
__device__ __half g_wa16[3*CC*CC];
__device__ __half g_wp16[CC*CC];
__device__ __half g_a16[MM*CC];          // attention output (fp16)

// ---------------------------------------------------------------------------
// Helpers
// ---------------------------------------------------------------------------
__device__ __forceinline__ uint32_t smem_u32(const void* p) {
    uint32_t r;
    asm("{ .reg .u64 t; cvta.to.shared.u64 t, %1; cvt.u32.u64 %0, t; }" : "=r"(r) : "l"(p));
    return r;
}
// bf16 mma (attention)
__device__ __forceinline__ void mma16816(float c[4], const uint32_t a[4], const uint32_t b0, const uint32_t b1) {
    asm volatile("mma.sync.aligned.m16n8k16.row.col.f32.bf16.bf16.f32 "
                 "{%0,%1,%2,%3}, {%4,%5,%6,%7}, {%8,%9}, {%0,%1,%2,%3};"
                 : "+f"(c[0]), "+f"(c[1]), "+f"(c[2]), "+f"(c[3])
                 : "r"(a[0]), "r"(a[1]), "r"(a[2]), "r"(a[3]), "r"(b0), "r"(b1));
}
// fp16 mma (dense GEMMs)
__device__ __forceinline__ void mma16816h(float c[4], const uint32_t a[4], const uint32_t b0, const uint32_t b1) {
    asm volatile("mma.sync.aligned.m16n8k16.row.col.f32.f16.f16.f32 "
                 "{%0,%1,%2,%3}, {%4,%5,%6,%7}, {%8,%9}, {%0,%1,%2,%3};"
                 : "+f"(c[0]), "+f"(c[1]), "+f"(c[2]), "+f"(c[3])
                 : "r"(a[0]), "r"(a[1]), "r"(a[2]), "r"(a[3]), "r"(b0), "r"(b1));
}
__device__ __forceinline__ void ldsm_x4(uint32_t r[4], uint32_t addr) {
    asm volatile("ldmatrix.sync.aligned.m8n8.x4.shared.b16 {%0,%1,%2,%3}, [%4];"
                 : "=r"(r[0]), "=r"(r[1]), "=r"(r[2]), "=r"(r[3]) : "r"(addr));
}
__device__ __forceinline__ void ldsm_x4t(uint32_t r[4], uint32_t addr) {
    asm volatile("ldmatrix.sync.aligned.m8n8.x4.trans.shared.b16 {%0,%1,%2,%3}, [%4];"
                 : "=r"(r[0]), "=r"(r[1]), "=r"(r[2]), "=r"(r[3]) : "r"(addr));
}
__device__ __forceinline__ void cp16(uint32_t smem, const void* g) {
    asm volatile("cp.async.cg.shared.global [%0], [%1], 16;" :: "r"(smem), "l"(g));
}
#define CP_COMMIT() asm volatile("cp.async.commit_group;" ::: "memory")
#define CP_WAIT1()  asm volatile("cp.async.wait_group 1;" ::: "memory")
#define CP_WAIT0()  asm volatile("cp.async.wait_group 0;" ::: "memory")

__device__ __forceinline__ uint32_t pack_bf2(__nv_bfloat16 lo, __nv_bfloat16 hi) {
    return ((uint32_t)__bfloat16_as_ushort(hi) << 16) | (uint32_t)__bfloat16_as_ushort(lo);
}
__device__ __forceinline__ void pack_split(float a, float b, uint32_t& h, uint32_t& l) {
    __nv_bfloat16 ha = __float2bfloat16(a), hb = __float2bfloat16(b);
    __nv_bfloat16 la = __float2bfloat16(a - __bfloat162float(ha));
    __nv_bfloat16 lb = __float2bfloat16(b - __bfloat162float(hb));
    h = pack_bf2(ha, hb);
    l = pack_bf2(la, lb);
}

// ---------------------------------------------------------------------------
// Convert fp32 -> fp16 (single)
// ---------------------------------------------------------------------------
__global__ __launch_bounds__(256) void conv16_kernel(
    const float* __restrict__ in, __half* __restrict__ out, int n)
{
    int i = (blockIdx.x * 256 + threadIdx.x) * 4;
    if (i >= n) return;
    float4 v = *(const float4*)(in + i);
    __half2 a = __floats2half2_rn(v.x, v.y);
    __half2 b = __floats2half2_rn(v.z, v.w);
    uint2 w;
    w.x = *(uint32_t*)&a; w.y = *(uint32_t*)&b;
    *(uint2*)(out + i) = w;
}

// ---------------------------------------------------------------------------
// Dense GEMM, single-pass fp16, fp32 accumulate. 128x128 tile, BK=64.
// MODE 0: scatter bf16 hi/lo into g_Q*/g_K*/g_V* (Q scaled). MODE 1: fp32 Cout.
// ---------------------------------------------------------------------------
#define GPAD 72
#define G_ARR (128*GPAD)          // 9216 halves per matrix
#define G_STAGE (2*G_ARR)         // A | B
#define GEMM_SMEM (2*G_STAGE*2)   // 73728 bytes

template<int MODE>
__global__ __launch_bounds__(256) void mma_gemm(
    const __half* __restrict__ A, const __half* __restrict__ B,
    const float* __restrict__ bias, float* __restrict__ Cout, int N)
{
    extern __shared__ __half smg[];
    const uint32_t sm_base = smem_u32(smg);

    const int tid  = threadIdx.x;
    const int lane = tid & 31;
    const int wid  = tid >> 5;
    const int wm   = wid & 3;
    const int wn   = wid >> 2;
    const int row0 = blockIdx.y * 128;
    const int col0 = blockIdx.x * 128;
    const int grp  = lane >> 2, qp = lane & 3;

    float acc[2][8][4];
#pragma unroll
    for (int mt = 0; mt < 2; mt++)
#pragma unroll
        for (int j = 0; j < 8; j++)
#pragma unroll
            for (int c = 0; c < 4; c++) acc[mt][j][c] = 0.f;

    const int arow_off = ((lane >> 3) & 1) * 8 + (lane & 7);
    const int acol_off = (lane >> 4) * 8;
    const int b4row = wn * 64 + ((lane >> 4) & 1) * 8 + (lane & 7);
    const int b4col = ((lane >> 3) & 1) * 8;

    auto fill = [&](int buf, int kt) {
        const uint32_t d0 = sm_base + buf * G_STAGE * 2;
#pragma unroll
        for (int u = 0; u < 8; u++) {
            const int idx = tid + u * 256;     // 0..2047
            const int arr = idx >> 10;         // 0 = A, 1 = B
            const int w   = idx & 1023;
            const int r   = w >> 3;
            const int c8  = (w & 7) * 8;
            const __half* src = (arr == 0)
                ? A + (size_t)(row0 + r) * KKC + kt + c8
                : B + (size_t)(col0 + r) * KKC + kt + c8;
            cp16(d0 + (arr * G_ARR + r * GPAD + c8) * 2, src);
        }
        CP_COMMIT();
    };

    fill(0, 0);
    const int NIT = KKC / 64;     // 12
    for (int it = 0; it < NIT; it++) {
        const int buf = it & 1;
        if (it + 1 < NIT) { fill(buf ^ 1, (it + 1) * 64); CP_WAIT1(); }
        else               CP_WAIT0();
        __syncthreads();

        const uint32_t sA = sm_base + (buf * G_STAGE) * 2;
        const uint32_t sB = sA + G_ARR * 2;

#pragma unroll
        for (int ks = 0; ks < 4; ks++) {
            uint32_t af[2][4];
#pragma unroll
            for (int mt = 0; mt < 2; mt++) {
                const int aoff = ((wm * 32 + mt * 16 + arow_off) * GPAD + ks * 16 + acol_off) * 2;
                ldsm_x4(af[mt], sA + aoff);
            }
#pragma unroll
            for (int jp = 0; jp < 4; jp++) {
                uint32_t b4[4];
                const int boff = ((b4row + jp * 16) * GPAD + ks * 16 + b4col) * 2;
                ldsm_x4(b4, sB + boff);
                mma16816h(acc[0][2*jp],   af[0], b4[0], b4[1]);
                mma16816h(acc[1][2*jp],   af[1], b4[0], b4[1]);
                mma16816h(acc[0][2*jp+1], af[0], b4[2], b4[3]);
                mma16816h(acc[1][2*jp+1], af[1], b4[2], b4[3]);
            }
        }
        __syncthreads();
    }

    // Epilogue
#pragma unroll
    for (int mt = 0; mt < 2; mt++) {
#pragma unroll
        for (int j = 0; j < 8; j++) {
            const int n = col0 + wn * 64 + j * 8 + qp * 2;
            const float b0 = bias[n], b1 = bias[n + 1];
#pragma unroll
            for (int rr = 0; rr < 2; rr++) {
                const int m = row0 + wm * 32 + mt * 16 + grp + rr * 8;
                float v0 = acc[mt][j][rr * 2 + 0] + b0;
                float v1 = acc[mt][j][rr * 2 + 1] + b1;
                if (MODE == 0) {
                    const int which = n / CC;
                    const int rm = n % CC;
                    const int h = rm / HS, e = rm % HS;
                    const int bb = m / TT, t = m % TT;
                    const size_t idx = ((size_t)(bb * HH + h) * TT + t) * HS + e;
                    uint32_t hw, lw;
                    if (which == 0) {
                        pack_split(v0 * SCALE_F, v1 * SCALE_F, hw, lw);
                        *(uint32_t*)&g_Qh[idx] = hw; *(uint32_t*)&g_Ql[idx] = lw;
                    } else if (which == 1) {
                        pack_split(v0, v1, hw, lw);
                        *(uint32_t*)&g_Kh[idx] = hw; *(uint32_t*)&g_Kl[idx] = lw;
                    } else {
                        pack_split(v0, v1, hw, lw);
                        *(uint32_t*)&g_Vh[idx] = hw; *(uint32_t*)&g_Vl[idx] = lw;
                    }
                } else {
                    float* p = Cout + (size_t)m * N + n;
                    *(float2*)p = make_float2(v0, v1);
                }
            }
        }
    }
}

// ---------------------------------------------------------------------------
// Flash attention (bf16 3-pass, R5 form). 1-D grid (768), LPT schedule.
// 8 warps x 16 q rows; Bc=64; Q fragments in SMEM; 2 CTAs/SM.
// ---------------------------------------------------------------------------
#define APAD 72
#define A_ARR (64*APAD)
#define A_STAGE (4*A_ARR)
#define QFRAG_B (8*4*8*32*4)
#define ATTN_SMEM (2*A_STAGE*2 + QFRAG_B)

__global__ __launch_bounds__(256, 2) void attn_mma()
{
    extern __shared__ __nv_bfloat16 smp[];
    const uint32_t sm_base = smem_u32(smp);
    uint32_t* qsm = (uint32_t*)((char*)smp + 2 * A_STAGE * 2);

    const int tid  = threadIdx.x;
    const int lane = tid & 31;
    const int wid  = tid >> 5;
    const int qi   = (TT/128 - 1) - (blockIdx.x / (BB*HH));
    const int bh   = blockIdx.x % (BB*HH);
    const int q0   = qi * 128;
    const int grp  = lane >> 2, qp = lane & 3;
    const int wr0  = q0 + wid * 16;

    const size_t bh_base = (size_t)bh * TT * HS;

    // Build Q fragments once -> per-warp SMEM
    {
#pragma unroll
        for (int ks = 0; ks < 4; ks++) {
            const int c0 = ks * 16 + qp * 2;
            const size_t r0 = bh_base + (size_t)(wr0 + grp) * HS;
            const size_t r1 = r0 + 8 * HS;
            uint32_t* q0p = &qsm[((wid * 4 + ks) * 8) * 32 + lane];
            q0p[0*32] = *(const uint32_t*)&g_Qh[r0 + c0];
            q0p[1*32] = *(const uint32_t*)&g_Qh[r1 + c0];
            q0p[2*32] = *(const uint32_t*)&g_Qh[r0 + c0 + 8];
            q0p[3*32] = *(const uint32_t*)&g_Qh[r1 + c0 + 8];
            q0p[4*32] = *(const uint32_t*)&g_Ql[r0 + c0];
            q0p[5*32] = *(const uint32_t*)&g_Ql[r1 + c0];
            q0p[6*32] = *(const uint32_t*)&g_Ql[r0 + c0 + 8];
            q0p[7*32] = *(const uint32_t*)&g_Ql[r1 + c0 + 8];
        }
    }

    float oacc[8][4];
    float mi[2] = {-1e30f, -1e30f}, li[2] = {0.f, 0.f};
#pragma unroll
    for (int j = 0; j < 8; j++)
#pragma unroll
        for (int c = 0; c < 4; c++) oacc[j][c] = 0.f;

    const int k4row = ((lane >> 4) & 1) * 8 + (lane & 7);
    const int k4col = ((lane >> 3) & 1) * 8;
    const int v4row = ((lane >> 3) & 1) * 8 + (lane & 7);
    const int v4col = ((lane >> 4) & 1) * 8;

    auto fillkv = [&](int buf, int k0) {
        const uint32_t d0 = sm_base + buf * A_STAGE * 2;
        const size_t gb = bh_base + (size_t)k0 * HS;
#pragma unroll
        for (int u = 0; u < 8; u++) {
            const int idx = tid + u * 256;
            const int arr = idx >> 9;
            const int w   = idx & 511;
            const int r   = w >> 3;
            const int c8  = (w & 7) * 8;
            const __nv_bfloat16* src =
                (arr == 0) ? g_Kh + gb + (size_t)r * HS + c8 :
                (arr == 1) ? g_Kl + gb + (size_t)r * HS + c8 :
                (arr == 2) ? g_Vh + gb + (size_t)r * HS + c8 :
                             g_Vl + gb + (size_t)r * HS + c8;
            cp16(d0 + (arr * A_ARR + r * APAD + c8) * 2, src);
        }
        CP_COMMIT();
    };

    const int niters = 2 * qi + 2;
    fillkv(0, 0);
    for (int kj = 0; kj < niters; kj++) {
        const int k0 = kj * 64;
        const int buf = kj & 1;
        if (kj + 1 < niters) { fillkv(buf ^ 1, (kj + 1) * 64); CP_WAIT1(); }
        else                   CP_WAIT0();
        __syncthreads();

        if (k0 <= wr0 + 15) {
            const uint32_t sKh = sm_base + (buf * A_STAGE) * 2;
            const uint32_t sKl = sKh + A_ARR * 2;
            const uint32_t sVh = sKh + 2 * A_ARR * 2;
            const uint32_t sVl = sKh + 3 * A_ARR * 2;

            // S = Q K^T
            float sacc[8][4];
#pragma unroll
            for (int j = 0; j < 8; j++)
#pragma unroll
                for (int c = 0; c < 4; c++) sacc[j][c] = 0.f;

#pragma unroll
            for (int ks = 0; ks < 4; ks++) {
                uint32_t qfh[4], qfl[4];
                const uint32_t* qp0 = &qsm[((wid * 4 + ks) * 8) * 32 + lane];
#pragma unroll
                for (int r = 0; r < 4; r++) { qfh[r] = qp0[r*32]; qfl[r] = qp0[(r+4)*32]; }
#pragma unroll
                for (int jp = 0; jp < 4; jp++) {
                    uint32_t kbh[4], kbl[4];
                    const int off = ((jp * 16 + k4row) * APAD + ks * 16 + k4col) * 2;
                    ldsm_x4(kbh, sKh + off);
                    ldsm_x4(kbl, sKl + off);
                    mma16816(sacc[2*jp],   qfh, kbh[0], kbh[1]);
                    mma16816(sacc[2*jp],   qfh, kbl[0], kbl[1]);
                    mma16816(sacc[2*jp],   qfl, kbh[0], kbh[1]);
                    mma16816(sacc[2*jp+1], qfh, kbh[2], kbh[3]);
                    mma16816(sacc[2*jp+1], qfh, kbl[2], kbl[3]);
                    mma16816(sacc[2*jp+1], qfl, kbh[2], kbh[3]);
                }
            }

            // Causal mask (partially-masked tiles only)
            if (k0 + 63 > wr0) {
#pragma unroll
                for (int j = 0; j < 8; j++) {
#pragma unroll
                    for (int c = 0; c < 4; c++) {
                        const int col = k0 + j * 8 + qp * 2 + (c & 1);
                        const int row = wr0 + grp + ((c >> 1) * 8);
                        if (col > row) sacc[j][c] = -1e30f;
                    }
                }
            }

            // Online softmax
#pragma unroll
            for (int rr = 0; rr < 2; rr++) {
                float mx = -1e30f;
#pragma unroll
                for (int j = 0; j < 8; j++) {
                    mx = fmaxf(mx, sacc[j][rr * 2]);
                    mx = fmaxf(mx, sacc[j][rr * 2 + 1]);
                }
                mx = fmaxf(mx, __shfl_xor_sync(0xffffffffu, mx, 1));
                mx = fmaxf(mx, __shfl_xor_sync(0xffffffffu, mx, 2));
                const float mnew = fmaxf(mi[rr], mx);
                const float corr = __expf(mi[rr] - mnew);
                float sum = 0.f;
#pragma unroll
                for (int j = 0; j < 8; j++) {
                    float p0 = __expf(sacc[j][rr * 2]     - mnew);
                    float p1 = __expf(sacc[j][rr * 2 + 1] - mnew);
                    sacc[j][rr * 2] = p0; sacc[j][rr * 2 + 1] = p1;
                    sum += p0 + p1;
                }
                sum += __shfl_xor_sync(0xffffffffu, sum, 1);
                sum += __shfl_xor_sync(0xffffffffu, sum, 2);
                li[rr] = li[rr] * corr + sum;
                mi[rr] = mnew;
#pragma unroll
                for (int j = 0; j < 8; j++) {
                    oacc[j][rr * 2]     *= corr;
                    oacc[j][rr * 2 + 1] *= corr;
                }
            }

            // P fragments in-register
            uint32_t ph[4][4], pl[4][4];
#pragma unroll
            for (int ks = 0; ks < 4; ks++) {
                const int j0 = 2 * ks, j1 = 2 * ks + 1;
                pack_split(sacc[j0][0], sacc[j0][1], ph[ks][0], pl[ks][0]);
                pack_split(sacc[j0][2], sacc[j0][3], ph[ks][1], pl[ks][1]);
                pack_split(sacc[j1][0], sacc[j1][1], ph[ks][2], pl[ks][2]);
                pack_split(sacc[j1][2], sacc[j1][3], ph[ks][3], pl[ks][3]);
            }

            // O += P V
#pragma unroll
            for (int ks = 0; ks < 4; ks++) {
#pragma unroll
                for (int jop = 0; jop < 4; jop++) {
                    uint32_t vbh[4], vbl[4];
                    const int off = ((ks * 16 + v4row) * APAD + (2*jop) * 8 + v4col) * 2;
                    ldsm_x4t(vbh, sVh + off);
                    ldsm_x4t(vbl, sVl + off);
                    mma16816(oacc[2*jop],   ph[ks], vbh[0], vbh[1]);
                    mma16816(oacc[2*jop],   ph[ks], vbl[0], vbl[1]);
                    mma16816(oacc[2*jop],   pl[ks], vbh[0], vbh[1]);
                    mma16816(oacc[2*jop+1], ph[ks], vbh[2], vbh[3]);
                    mma16816(oacc[2*jop+1], ph[ks], vbl[2], vbl[3]);
                    mma16816(oacc[2*jop+1], pl[ks], vbh[2], vbh[3]);
                }
            }
        }
        __syncthreads();
    }

    // Epilogue: write fp16 O directly (feeds fp16 projection GEMM)
    const int b = bh / HH, h = bh % HH;
#pragma unroll
    for (int rr = 0; rr < 2; rr++) {
        const int t = wr0 + grp + rr * 8;
        const float inv = 1.f / li[rr];
        const size_t base = (size_t)(b * TT + t) * CC + h * HS;
#pragma unroll
        for (int jo = 0; jo < 8; jo++) {
            __half2 hv = __floats2half2_rn(oacc[jo][rr * 2] * inv,
                                           oacc[jo][rr * 2 + 1] * inv);
            *(__half2*)&g_a16[base + jo * 8 + qp * 2] = hv;
        }
    }
}

// ---------------------------------------------------------------------------
extern "C" void kernel_launch(void* const* d_in, const int* in_sizes, int n_in,
                              void* d_out, int out_size)
{
    const float* x      = (const float*)d_in[0];
    const float* w_attn = (const float*)d_in[1];
    const float* b_attn = (const float*)d_in[2];
    const float* w_proj = (const float*)d_in[3];
    const float* b_proj = (const float*)d_in[4];
    float* out = (float*)d_out;
    (void)in_sizes; (void)n_in; (void)out_size;

    __half *x16, *wa16, *wp16, *a16;
    cudaGetSymbolAddress((void**)&x16,  g_x16);
    cudaGetSymbolAddress((void**)&wa16, g_wa16);
    cudaGetSymbolAddress((void**)&wp16, g_wp16);
    cudaGetSymbolAddress((void**)&a16,  g_a16);

    cudaFuncSetAttribute(mma_gemm<0>, cudaFuncAttributeMaxDynamicSharedMemorySize, GEMM_SMEM);
    cudaFuncSetAttribute(mma_gemm<1>, cudaFuncAttributeMaxDynamicSharedMemorySize, GEMM_SMEM);
    cudaFuncSetAttribute(attn_mma,    cudaFuncAttributeMaxDynamicSharedMemorySize, ATTN_SMEM);

    // 0) convert inputs to fp16
    conv16_kernel<<<(MM*CC/4 + 255)/256, 256>>>(x, x16, MM*CC);
    conv16_kernel<<<(3*CC*CC/4 + 255)/256, 256>>>(w_attn, wa16, 3*CC*CC);
    conv16_kernel<<<(CC*CC/4 + 255)/256, 256>>>(w_proj, wp16, CC*CC);

    // 1) QKV projection (fp16 single-pass) -> bf16 hi/lo Q/K/V
    mma_gemm<0><<<dim3(3*CC/128, MM/128), 256, GEMM_SMEM>>>(x16, wa16, b_attn, nullptr, 3*CC);

    // 2) Flash attention (bf16 3-pass, LPT)
    attn_mma<<<(TT/128) * BB * HH, 256, ATTN_SMEM>>>();

    // 3) Output projection (fp16 single-pass)
    mma_gemm<1><<<dim3(CC/128, MM/128), 256, GEMM_SMEM>>>(a16, wp16, b_proj, out, CC);
}

// round 8
// speedup vs baseline: 1.6834x; 1.2798x over previous
#include <cuda_runtime.h>
#include <cuda_bf16.h>
#include <cuda_fp16.h>
#include <cstdint>

// Problem constants
#define BB 2
#define TT 4096
#define CC 768
#define HH 12
#define HS 64
#define MM (BB*TT)          // 8192
#define KKC 768
#define SCALE_F 0.125f      // HS^-0.5

// ---------------------------------------------------------------------------
// Scratch (allocation-free: __device__ globals)
// ---------------------------------------------------------------------------
__device__ __half g_Q16[BB*HH*TT*HS];                       // scaled Q (fp16)
__device__ __half g_Kh16[BB*HH*TT*HS], g_Kl16[BB*HH*TT*HS]; // K hi/lo fp16
__device__ __half g_Vh16[BB*HH*TT*HS], g_Vl16[BB*HH*TT*HS]; // V hi/lo fp16
__device__ __half g_x16[MM*CC];
__device__ __half g_wa16[3*CC*CC];
__device__ __half g_wp16[CC*CC];
__device__ __half g_a16[MM*CC];                             // attn out (fp16)

// ---------------------------------------------------------------------------
// Helpers
// ---------------------------------------------------------------------------
__device__ __forceinline__ uint32_t smem_u32(const void* p) {
    uint32_t r;
    asm("{ .reg .u64 t; cvta.to.shared.u64 t, %1; cvt.u32.u64 %0, t; }" : "=r"(r) : "l"(p));
    return r;
}
__device__ __forceinline__ void mma16816h(float c[4], const uint32_t a[4], const uint32_t b0, const uint32_t b1) {
    asm volatile("mma.sync.aligned.m16n8k16.row.col.f32.f16.f16.f32 "
                 "{%0,%1,%2,%3}, {%4,%5,%6,%7}, {%8,%9}, {%0,%1,%2,%3};"
                 : "+f"(c[0]), "+f"(c[1]), "+f"(c[2]), "+f"(c[3])
                 : "r"(a[0]), "r"(a[1]), "r"(a[2]), "r"(a[3]), "r"(b0), "r"(b1));
}
__device__ __forceinline__ void ldsm_x4(uint32_t r[4], uint32_t addr) {
    asm volatile("ldmatrix.sync.aligned.m8n8.x4.shared.b16 {%0,%1,%2,%3}, [%4];"
                 : "=r"(r[0]), "=r"(r[1]), "=r"(r[2]), "=r"(r[3]) : "r"(addr));
}
__device__ __forceinline__ void ldsm_x4t(uint32_t r[4], uint32_t addr) {
    asm volatile("ldmatrix.sync.aligned.m8n8.x4.trans.shared.b16 {%0,%1,%2,%3}, [%4];"
                 : "=r"(r[0]), "=r"(r[1]), "=r"(r[2]), "=r"(r[3]) : "r"(addr));
}
__device__ __forceinline__ void cp16(uint32_t smem, const void* g) {
    asm volatile("cp.async.cg.shared.global [%0], [%1], 16;" :: "r"(smem), "l"(g));
}
#define CP_COMMIT() asm volatile("cp.async.commit_group;" ::: "memory")
#define CP_WAIT1()  asm volatile("cp.async.wait_group 1;" ::: "memory")
#define CP_WAIT0()  asm volatile("cp.async.wait_group 0;" ::: "memory")

__device__ __forceinline__ uint32_t pack_h2(float a, float b) {
    __half2 h = __floats2half2_rn(a, b);
    return *(uint32_t*)&h;
}
__device__ __forceinline__ void pack_split16(float a, float b, uint32_t& h, uint32_t& l) {
    __half ha = __float2half_rn(a), hb = __float2half_rn(b);
    __half la = __float2half_rn(a - __half2float(ha));
    __half lb = __float2half_rn(b - __half2float(hb));
    h = ((uint32_t)__half_as_ushort(hb) << 16) | (uint32_t)__half_as_ushort(ha);
    l = ((uint32_t)__half_as_ushort(lb) << 16) | (uint32_t)__half_as_ushort(la);
}

// ---------------------------------------------------------------------------
// Convert fp32 -> fp16
// ---------------------------------------------------------------------------
__global__ __launch_bounds__(256) void conv16_kernel(
    const float* __restrict__ in, __half* __restrict__ out, int n)
{
    int i = (blockIdx.x * 256 + threadIdx.x) * 4;
    if (i >= n) return;
    float4 v = *(const float4*)(in + i);
    uint2 w;
    w.x = pack_h2(v.x, v.y);
    w.y = pack_h2(v.z, v.w);
    *(uint2*)(out + i) = w;
}

// ---------------------------------------------------------------------------
// Dense GEMM, single-pass fp16, fp32 accumulate. 128x128 tile, BK=64,
// 3-stage cp.async ring, one barrier per iteration.
// MODE 0: scatter fp16 Q (scaled) / K,V hi+lo. MODE 1: fp32 Cout.
// ---------------------------------------------------------------------------
#define GPAD 72
#define G_ARR (128*GPAD)          // 9216 halves per matrix
#define G_STAGE (2*G_ARR)         // A | B
#define GEMM_SMEM (3*G_STAGE*2)   // 110592 bytes (3 stages)

template<int MODE>
__global__ __launch_bounds__(256) void mma_gemm(
    const __half* __restrict__ A, const __half* __restrict__ B,
    const float* __restrict__ bias, float* __restrict__ Cout, int N)
{
    extern __shared__ __half smg[];
    const uint32_t sm_base = smem_u32(smg);

    const int tid  = threadIdx.x;
    const int lane = tid & 31;
    const int wid  = tid >> 5;
    const int wm   = wid & 3;
    const int wn   = wid >> 2;
    const int row0 = blockIdx.y * 128;
    const int col0 = blockIdx.x * 128;
    const int grp  = lane >> 2, qp = lane & 3;

    float acc[2][8][4];
#pragma unroll
    for (int mt = 0; mt < 2; mt++)
#pragma unroll
        for (int j = 0; j < 8; j++)
#pragma unroll
            for (int c = 0; c < 4; c++) acc[mt][j][c] = 0.f;

    const int arow_off = ((lane >> 3) & 1) * 8 + (lane & 7);
    const int acol_off = (lane >> 4) * 8;
    const int b4row = wn * 64 + ((lane >> 4) & 1) * 8 + (lane & 7);
    const int b4col = ((lane >> 3) & 1) * 8;

    auto fill = [&](int stg, int kt) {
        const uint32_t d0 = sm_base + stg * G_STAGE * 2;
#pragma unroll
        for (int u = 0; u < 8; u++) {
            const int idx = tid + u * 256;     // 0..2047
            const int arr = idx >> 10;         // 0 = A, 1 = B
            const int w   = idx & 1023;
            const int r   = w >> 3;
            const int c8  = (w & 7) * 8;
            const __half* src = (arr == 0)
                ? A + (size_t)(row0 + r) * KKC + kt + c8
                : B + (size_t)(col0 + r) * KKC + kt + c8;
            cp16(d0 + (arr * G_ARR + r * GPAD + c8) * 2, src);
        }
        CP_COMMIT();
    };

    const int NIT = KKC / 64;     // 12
    fill(0, 0);
    fill(1, 64);
    for (int it = 0; it < NIT; it++) {
        if (it + 1 < NIT) CP_WAIT1(); else CP_WAIT0();
        __syncthreads();
        if (it + 2 < NIT) fill((it + 2) % 3, (it + 2) * 64);

        const uint32_t sA = sm_base + ((it % 3) * G_STAGE) * 2;
        const uint32_t sB = sA + G_ARR * 2;

#pragma unroll
        for (int ks = 0; ks < 4; ks++) {
            uint32_t af[2][4];
#pragma unroll
            for (int mt = 0; mt < 2; mt++) {
                const int aoff = ((wm * 32 + mt * 16 + arow_off) * GPAD + ks * 16 + acol_off) * 2;
                ldsm_x4(af[mt], sA + aoff);
            }
#pragma unroll
            for (int jp = 0; jp < 4; jp++) {
                uint32_t b4[4];
                const int boff = ((b4row + jp * 16) * GPAD + ks * 16 + b4col) * 2;
                ldsm_x4(b4, sB + boff);
                mma16816h(acc[0][2*jp],   af[0], b4[0], b4[1]);
                mma16816h(acc[1][2*jp],   af[1], b4[0], b4[1]);
                mma16816h(acc[0][2*jp+1], af[0], b4[2], b4[3]);
                mma16816h(acc[1][2*jp+1], af[1], b4[2], b4[3]);
            }
        }
    }

    // Epilogue
#pragma unroll
    for (int mt = 0; mt < 2; mt++) {
#pragma unroll
        for (int j = 0; j < 8; j++) {
            const int n = col0 + wn * 64 + j * 8 + qp * 2;
            const float b0 = bias[n], b1 = bias[n + 1];
#pragma unroll
            for (int rr = 0; rr < 2; rr++) {
                const int m = row0 + wm * 32 + mt * 16 + grp + rr * 8;
                float v0 = acc[mt][j][rr * 2 + 0] + b0;
                float v1 = acc[mt][j][rr * 2 + 1] + b1;
                if (MODE == 0) {
                    const int which = n / CC;
                    const int rm = n % CC;
                    const int h = rm / HS, e = rm % HS;
                    const int bb = m / TT, t = m % TT;
                    const size_t idx = ((size_t)(bb * HH + h) * TT + t) * HS + e;
                    if (which == 0) {
                        *(uint32_t*)&g_Q16[idx] = pack_h2(v0 * SCALE_F, v1 * SCALE_F);
                    } else if (which == 1) {
                        uint32_t hw, lw;
                        pack_split16(v0, v1, hw, lw);
                        *(uint32_t*)&g_Kh16[idx] = hw; *(uint32_t*)&g_Kl16[idx] = lw;
                    } else {
                        uint32_t hw, lw;
                        pack_split16(v0, v1, hw, lw);
                        *(uint32_t*)&g_Vh16[idx] = hw; *(uint32_t*)&g_Vl16[idx] = lw;
                    }
                } else {
                    float* p = Cout + (size_t)m * N + n;
                    *(float2*)p = make_float2(v0, v1);
                }
            }
        }
    }
}

// ---------------------------------------------------------------------------
// Flash attention, fp16 2-pass both phases: S = qh*(kh+kl), O += p16*(vh+vl).
// 1-D grid (768), LPT schedule. 8 warps x 16 q rows; Bc=64; 2 CTAs/SM.
// ---------------------------------------------------------------------------
#define APAD 72
#define A_ARR (64*APAD)
#define A_STAGE (4*A_ARR)                 // Kh|Kl|Vh|Vl
#define QFRAG_B (8*4*4*32*4)              // 16384 bytes (qh only)
#define ATTN_SMEM (2*A_STAGE*2 + QFRAG_B) // 73728 + 16384 = 90112

__global__ __launch_bounds__(256, 2) void attn_mma()
{
    extern __shared__ __half smp[];
    const uint32_t sm_base = smem_u32(smp);
    uint32_t* qsm = (uint32_t*)((char*)smp + 2 * A_STAGE * 2);

    const int tid  = threadIdx.x;
    const int lane = tid & 31;
    const int wid  = tid >> 5;
    const int qi   = (TT/128 - 1) - (blockIdx.x / (BB*HH));
    const int bh   = blockIdx.x % (BB*HH);
    const int q0   = qi * 128;
    const int grp  = lane >> 2, qp = lane & 3;
    const int wr0  = q0 + wid * 16;

    const size_t bh_base = (size_t)bh * TT * HS;

    // Build Q fragments once -> per-warp SMEM (hi only)
    {
#pragma unroll
        for (int ks = 0; ks < 4; ks++) {
            const int c0 = ks * 16 + qp * 2;
            const size_t r0 = bh_base + (size_t)(wr0 + grp) * HS;
            const size_t r1 = r0 + 8 * HS;
            uint32_t* q0p = &qsm[((wid * 4 + ks) * 4) * 32 + lane];
            q0p[0*32] = *(const uint32_t*)&g_Q16[r0 + c0];
            q0p[1*32] = *(const uint32_t*)&g_Q16[r1 + c0];
            q0p[2*32] = *(const uint32_t*)&g_Q16[r0 + c0 + 8];
            q0p[3*32] = *(const uint32_t*)&g_Q16[r1 + c0 + 8];
        }
    }

    float oacc[8][4];
    float mi[2] = {-1e30f, -1e30f}, li[2] = {0.f, 0.f};
#pragma unroll
    for (int j = 0; j < 8; j++)
#pragma unroll
        for (int c = 0; c < 4; c++) oacc[j][c] = 0.f;

    const int k4row = ((lane >> 4) & 1) * 8 + (lane & 7);
    const int k4col = ((lane >> 3) & 1) * 8;
    const int v4row = ((lane >> 3) & 1) * 8 + (lane & 7);
    const int v4col = ((lane >> 4) & 1) * 8;

    auto fillkv = [&](int buf, int k0) {
        const uint32_t d0 = sm_base + buf * A_STAGE * 2;
        const size_t gb = bh_base + (size_t)k0 * HS;
#pragma unroll
        for (int u = 0; u < 8; u++) {
            const int idx = tid + u * 256;
            const int arr = idx >> 9;
            const int w   = idx & 511;
            const int r   = w >> 3;
            const int c8  = (w & 7) * 8;
            const __half* src =
                (arr == 0) ? g_Kh16 + gb + (size_t)r * HS + c8 :
                (arr == 1) ? g_Kl16 + gb + (size_t)r * HS + c8 :
                (arr == 2) ? g_Vh16 + gb + (size_t)r * HS + c8 :
                             g_Vl16 + gb + (size_t)r * HS + c8;
            cp16(d0 + (arr * A_ARR + r * APAD + c8) * 2, src);
        }
        CP_COMMIT();
    };

    const int niters = 2 * qi + 2;
    fillkv(0, 0);
    for (int kj = 0; kj < niters; kj++) {
        const int k0 = kj * 64;
        const int buf = kj & 1;
        if (kj + 1 < niters) { fillkv(buf ^ 1, (kj + 1) * 64); CP_WAIT1(); }
        else                   CP_WAIT0();
        __syncthreads();

        if (k0 <= wr0 + 15) {
            const uint32_t sKh = sm_base + (buf * A_STAGE) * 2;
            const uint32_t sKl = sKh + A_ARR * 2;
            const uint32_t sVh = sKh + 2 * A_ARR * 2;
            const uint32_t sVl = sKh + 3 * A_ARR * 2;

            // S = qh * (kh + kl)   [2 passes]
            float sacc[8][4];
#pragma unroll
            for (int j = 0; j < 8; j++)
#pragma unroll
                for (int c = 0; c < 4; c++) sacc[j][c] = 0.f;

#pragma unroll
            for (int ks = 0; ks < 4; ks++) {
                uint32_t qf[4];
                const uint32_t* qp0 = &qsm[((wid * 4 + ks) * 4) * 32 + lane];
#pragma unroll
                for (int r = 0; r < 4; r++) qf[r] = qp0[r*32];
#pragma unroll
                for (int jp = 0; jp < 4; jp++) {
                    uint32_t kbh[4], kbl[4];
                    const int off = ((jp * 16 + k4row) * APAD + ks * 16 + k4col) * 2;
                    ldsm_x4(kbh, sKh + off);
                    ldsm_x4(kbl, sKl + off);
                    mma16816h(sacc[2*jp],   qf, kbh[0], kbh[1]);
                    mma16816h(sacc[2*jp+1], qf, kbh[2], kbh[3]);
                    mma16816h(sacc[2*jp],   qf, kbl[0], kbl[1]);
                    mma16816h(sacc[2*jp+1], qf, kbl[2], kbl[3]);
                }
            }

            // Causal mask (partially-masked tiles only)
            if (k0 + 63 > wr0) {
#pragma unroll
                for (int j = 0; j < 8; j++) {
#pragma unroll
                    for (int c = 0; c < 4; c++) {
                        const int col = k0 + j * 8 + qp * 2 + (c & 1);
                        const int row = wr0 + grp + ((c >> 1) * 8);
                        if (col > row) sacc[j][c] = -1e30f;
                    }
                }
            }

            // Online softmax
#pragma unroll
            for (int rr = 0; rr < 2; rr++) {
                float mx = -1e30f;
#pragma unroll
                for (int j = 0; j < 8; j++) {
                    mx = fmaxf(mx, sacc[j][rr * 2]);
                    mx = fmaxf(mx, sacc[j][rr * 2 + 1]);
                }
                mx = fmaxf(mx, __shfl_xor_sync(0xffffffffu, mx, 1));
                mx = fmaxf(mx, __shfl_xor_sync(0xffffffffu, mx, 2));
                const float mnew = fmaxf(mi[rr], mx);
                const float corr = __expf(mi[rr] - mnew);
                float sum = 0.f;
#pragma unroll
                for (int j = 0; j < 8; j++) {
                    float p0 = __expf(sacc[j][rr * 2]     - mnew);
                    float p1 = __expf(sacc[j][rr * 2 + 1] - mnew);
                    sacc[j][rr * 2] = p0; sacc[j][rr * 2 + 1] = p1;
                    sum += p0 + p1;
                }
                sum += __shfl_xor_sync(0xffffffffu, sum, 1);
                sum += __shfl_xor_sync(0xffffffffu, sum, 2);
                li[rr] = li[rr] * corr + sum;
                mi[rr] = mnew;
#pragma unroll
                for (int j = 0; j < 8; j++) {
                    oacc[j][rr * 2]     *= corr;
                    oacc[j][rr * 2 + 1] *= corr;
                }
            }

            // P fragments (fp16, single)
            uint32_t ph[4][4];
#pragma unroll
            for (int ks = 0; ks < 4; ks++) {
                const int j0 = 2 * ks, j1 = 2 * ks + 1;
                ph[ks][0] = pack_h2(sacc[j0][0], sacc[j0][1]);
                ph[ks][1] = pack_h2(sacc[j0][2], sacc[j0][3]);
                ph[ks][2] = pack_h2(sacc[j1][0], sacc[j1][1]);
                ph[ks][3] = pack_h2(sacc[j1][2], sacc[j1][3]);
            }

            // O += p16 * (vh + vl)   [2 passes]
#pragma unroll
            for (int ks = 0; ks < 4; ks++) {
#pragma unroll
                for (int jop = 0; jop < 4; jop++) {
                    uint32_t vbh[4], vbl[4];
                    const int off = ((ks * 16 + v4row) * APAD + (2*jop) * 8 + v4col) * 2;
                    ldsm_x4t(vbh, sVh + off);
                    ldsm_x4t(vbl, sVl + off);
                    mma16816h(oacc[2*jop],   ph[ks], vbh[0], vbh[1]);
                    mma16816h(oacc[2*jop+1], ph[ks], vbh[2], vbh[3]);
                    mma16816h(oacc[2*jop],   ph[ks], vbl[0], vbl[1]);
                    mma16816h(oacc[2*jop+1], ph[ks], vbl[2], vbl[3]);
                }
            }
        }
        __syncthreads();
    }

    // Epilogue: write fp16 O (feeds fp16 projection GEMM)
    const int b = bh / HH, h = bh % HH;
#pragma unroll
    for (int rr = 0; rr < 2; rr++) {
        const int t = wr0 + grp + rr * 8;
        const float inv = 1.f / li[rr];
        const size_t base = (size_t)(b * TT + t) * CC + h * HS;
#pragma unroll
        for (int jo = 0; jo < 8; jo++) {
            *(uint32_t*)&g_a16[base + jo * 8 + qp * 2] =
                pack_h2(oacc[jo][rr * 2] * inv, oacc[jo][rr * 2 + 1] * inv);
        }
    }
}

// ---------------------------------------------------------------------------
extern "C" void kernel_launch(void* const* d_in, const int* in_sizes, int n_in,
                              void* d_out, int out_size)
{
    const float* x      = (const float*)d_in[0];
    const float* w_attn = (const float*)d_in[1];
    const float* b_attn = (const float*)d_in[2];
    const float* w_proj = (const float*)d_in[3];
    const float* b_proj = (const float*)d_in[4];
    float* out = (float*)d_out;
    (void)in_sizes; (void)n_in; (void)out_size;

    __half *x16, *wa16, *wp16, *a16;
    cudaGetSymbolAddress((void**)&x16,  g_x16);
    cudaGetSymbolAddress((void**)&wa16, g_wa16);
    cudaGetSymbolAddress((void**)&wp16, g_wp16);
    cudaGetSymbolAddress((void**)&a16,  g_a16);

    cudaFuncSetAttribute(mma_gemm<0>, cudaFuncAttributeMaxDynamicSharedMemorySize, GEMM_SMEM);
    cudaFuncSetAttribute(mma_gemm<1>, cudaFuncAttributeMaxDynamicSharedMemorySize, GEMM_SMEM);
    cudaFuncSetAttribute(attn_mma,    cudaFuncAttributeMaxDynamicSharedMemorySize, ATTN_SMEM);

    // 0) convert inputs to fp16
    conv16_kernel<<<(MM*CC/4 + 255)/256, 256>>>(x, x16, MM*CC);
    conv16_kernel<<<(3*CC*CC/4 + 255)/256, 256>>>(w_attn, wa16, 3*CC*CC);
    conv16_kernel<<<(CC*CC/4 + 255)/256, 256>>>(w_proj, wp16, CC*CC);

    // 1) QKV projection (fp16 single-pass) -> Q16 scaled, K/V hi+lo fp16
    mma_gemm<0><<<dim3(3*CC/128, MM/128), 256, GEMM_SMEM>>>(x16, wa16, b_attn, nullptr, 3*CC);

    // 2) Flash attention (fp16 2-pass, LPT)
    attn_mma<<<(TT/128) * BB * HH, 256, ATTN_SMEM>>>();

    // 3) Output projection (fp16 single-pass)
    mma_gemm<1><<<dim3(CC/128, MM/128), 256, GEMM_SMEM>>>(a16, wp16, b_proj, out, CC);
}

// round 9
// speedup vs baseline: 2.3157x; 1.3756x over previous
#include <cuda_runtime.h>
#include <cuda_bf16.h>
#include <cuda_fp16.h>
#include <cstdint>

// Problem constants
#define BB 2
#define TT 4096
#define CC 768
#define HH 12
#define HS 64
#define MM (BB*TT)          // 8192
#define KKC 768
#define SCALE_F 0.125f      // HS^-0.5

// ---------------------------------------------------------------------------
// Scratch (allocation-free: __device__ globals)
// ---------------------------------------------------------------------------
__device__ __half g_Q16[BB*HH*TT*HS];   // scaled Q (fp16)
__device__ __half g_K16[BB*HH*TT*HS];   // K (fp16)
__device__ __half g_V16[BB*HH*TT*HS];   // V (fp16)
__device__ __half g_x16[MM*CC];
__device__ __half g_wa16[3*CC*CC];
__device__ __half g_wp16[CC*CC];
__device__ __half g_a16[MM*CC];         // attn out (fp16)

// ---------------------------------------------------------------------------
// Helpers
// ---------------------------------------------------------------------------
__device__ __forceinline__ uint32_t smem_u32(const void* p) {
    uint32_t r;
    asm("{ .reg .u64 t; cvta.to.shared.u64 t, %1; cvt.u32.u64 %0, t; }" : "=r"(r) : "l"(p));
    return r;
}
__device__ __forceinline__ void mma16816h(float c[4], const uint32_t a[4], const uint32_t b0, const uint32_t b1) {
    asm volatile("mma.sync.aligned.m16n8k16.row.col.f32.f16.f16.f32 "
                 "{%0,%1,%2,%3}, {%4,%5,%6,%7}, {%8,%9}, {%0,%1,%2,%3};"
                 : "+f"(c[0]), "+f"(c[1]), "+f"(c[2]), "+f"(c[3])
                 : "r"(a[0]), "r"(a[1]), "r"(a[2]), "r"(a[3]), "r"(b0), "r"(b1));
}
__device__ __forceinline__ void ldsm_x4(uint32_t r[4], uint32_t addr) {
    asm volatile("ldmatrix.sync.aligned.m8n8.x4.shared.b16 {%0,%1,%2,%3}, [%4];"
                 : "=r"(r[0]), "=r"(r[1]), "=r"(r[2]), "=r"(r[3]) : "r"(addr));
}
__device__ __forceinline__ void ldsm_x4t(uint32_t r[4], uint32_t addr) {
    asm volatile("ldmatrix.sync.aligned.m8n8.x4.trans.shared.b16 {%0,%1,%2,%3}, [%4];"
                 : "=r"(r[0]), "=r"(r[1]), "=r"(r[2]), "=r"(r[3]) : "r"(addr));
}
__device__ __forceinline__ void cp16(uint32_t smem, const void* g) {
    asm volatile("cp.async.cg.shared.global [%0], [%1], 16;" :: "r"(smem), "l"(g));
}
#define CP_COMMIT() asm volatile("cp.async.commit_group;" ::: "memory")
#define CP_WAIT1()  asm volatile("cp.async.wait_group 1;" ::: "memory")
#define CP_WAIT0()  asm volatile("cp.async.wait_group 0;" ::: "memory")

__device__ __forceinline__ uint32_t pack_h2(float a, float b) {
    __half2 h = __floats2half2_rn(a, b);
    return *(uint32_t*)&h;
}

// ---------------------------------------------------------------------------
// Convert fp32 -> fp16
// ---------------------------------------------------------------------------
__global__ __launch_bounds__(256) void conv16_kernel(
    const float* __restrict__ in, __half* __restrict__ out, int n)
{
    int i = (blockIdx.x * 256 + threadIdx.x) * 4;
    if (i >= n) return;
    float4 v = *(const float4*)(in + i);
    uint2 w;
    w.x = pack_h2(v.x, v.y);
    w.y = pack_h2(v.z, v.w);
    *(uint2*)(out + i) = w;
}

// ---------------------------------------------------------------------------
// Dense GEMM, single-pass fp16, fp32 accumulate. 128x128 tile, BK=64,
// 3-stage cp.async ring. MODE 0: scatter fp16 Q(scaled)/K/V. MODE 1: fp32 Cout.
// ---------------------------------------------------------------------------
#define GPAD 72
#define G_ARR (128*GPAD)
#define G_STAGE (2*G_ARR)
#define GEMM_SMEM (3*G_STAGE*2)

template<int MODE>
__global__ __launch_bounds__(256) void mma_gemm(
    const __half* __restrict__ A, const __half* __restrict__ B,
    const float* __restrict__ bias, float* __restrict__ Cout, int N)
{
    extern __shared__ __half smg[];
    const uint32_t sm_base = smem_u32(smg);

    const int tid  = threadIdx.x;
    const int lane = tid & 31;
    const int wid  = tid >> 5;
    const int wm   = wid & 3;
    const int wn   = wid >> 2;
    const int row0 = blockIdx.y * 128;
    const int col0 = blockIdx.x * 128;
    const int grp  = lane >> 2, qp = lane & 3;

    float acc[2][8][4];
#pragma unroll
    for (int mt = 0; mt < 2; mt++)
#pragma unroll
        for (int j = 0; j < 8; j++)
#pragma unroll
            for (int c = 0; c < 4; c++) acc[mt][j][c] = 0.f;

    const int arow_off = ((lane >> 3) & 1) * 8 + (lane & 7);
    const int acol_off = (lane >> 4) * 8;
    const int b4row = wn * 64 + ((lane >> 4) & 1) * 8 + (lane & 7);
    const int b4col = ((lane >> 3) & 1) * 8;

    auto fill = [&](int stg, int kt) {
        const uint32_t d0 = sm_base + stg * G_STAGE * 2;
#pragma unroll
        for (int u = 0; u < 8; u++) {
            const int idx = tid + u * 256;
            const int arr = idx >> 10;
            const int w   = idx & 1023;
            const int r   = w >> 3;
            const int c8  = (w & 7) * 8;
            const __half* src = (arr == 0)
                ? A + (size_t)(row0 + r) * KKC + kt + c8
                : B + (size_t)(col0 + r) * KKC + kt + c8;
            cp16(d0 + (arr * G_ARR + r * GPAD + c8) * 2, src);
        }
        CP_COMMIT();
    };

    const int NIT = KKC / 64;     // 12
    fill(0, 0);
    fill(1, 64);
    for (int it = 0; it < NIT; it++) {
        if (it + 1 < NIT) CP_WAIT1(); else CP_WAIT0();
        __syncthreads();
        if (it + 2 < NIT) fill((it + 2) % 3, (it + 2) * 64);

        const uint32_t sA = sm_base + ((it % 3) * G_STAGE) * 2;
        const uint32_t sB = sA + G_ARR * 2;

#pragma unroll
        for (int ks = 0; ks < 4; ks++) {
            uint32_t af[2][4];
#pragma unroll
            for (int mt = 0; mt < 2; mt++) {
                const int aoff = ((wm * 32 + mt * 16 + arow_off) * GPAD + ks * 16 + acol_off) * 2;
                ldsm_x4(af[mt], sA + aoff);
            }
#pragma unroll
            for (int jp = 0; jp < 4; jp++) {
                uint32_t b4[4];
                const int boff = ((b4row + jp * 16) * GPAD + ks * 16 + b4col) * 2;
                ldsm_x4(b4, sB + boff);
                mma16816h(acc[0][2*jp],   af[0], b4[0], b4[1]);
                mma16816h(acc[1][2*jp],   af[1], b4[0], b4[1]);
                mma16816h(acc[0][2*jp+1], af[0], b4[2], b4[3]);
                mma16816h(acc[1][2*jp+1], af[1], b4[2], b4[3]);
            }
        }
    }

    // Epilogue
#pragma unroll
    for (int mt = 0; mt < 2; mt++) {
#pragma unroll
        for (int j = 0; j < 8; j++) {
            const int n = col0 + wn * 64 + j * 8 + qp * 2;
            const float b0 = bias[n], b1 = bias[n + 1];
#pragma unroll
            for (int rr = 0; rr < 2; rr++) {
                const int m = row0 + wm * 32 + mt * 16 + grp + rr * 8;
                float v0 = acc[mt][j][rr * 2 + 0] + b0;
                float v1 = acc[mt][j][rr * 2 + 1] + b1;
                if (MODE == 0) {
                    const int which = n / CC;
                    const int rm = n % CC;
                    const int h = rm / HS, e = rm % HS;
                    const int bb = m / TT, t = m % TT;
                    const size_t idx = ((size_t)(bb * HH + h) * TT + t) * HS + e;
                    if (which == 0) {
                        *(uint32_t*)&g_Q16[idx] = pack_h2(v0 * SCALE_F, v1 * SCALE_F);
                    } else if (which == 1) {
                        *(uint32_t*)&g_K16[idx] = pack_h2(v0, v1);
                    } else {
                        *(uint32_t*)&g_V16[idx] = pack_h2(v0, v1);
                    }
                } else {
                    float* p = Cout + (size_t)m * N + n;
                    *(float2*)p = make_float2(v0, v1);
                }
            }
        }
    }
}

// ---------------------------------------------------------------------------
// Flash attention, pure single-pass fp16 (fp32 accumulate).
// 1-D grid (768), LPT schedule. 8 warps x 16 q rows; Bc=64; 2 CTAs/SM.
// ---------------------------------------------------------------------------
#define APAD 72
#define A_ARR (64*APAD)
#define A_STAGE (2*A_ARR)                 // K | V
#define QFRAG_B (8*4*4*32*4)              // 16384 bytes (q fp16 frags)
#define ATTN_SMEM (2*A_STAGE*2 + QFRAG_B) // 36864 + 16384 = 53248

__global__ __launch_bounds__(256, 2) void attn_mma()
{
    extern __shared__ __half smp[];
    const uint32_t sm_base = smem_u32(smp);
    uint32_t* qsm = (uint32_t*)((char*)smp + 2 * A_STAGE * 2);

    const int tid  = threadIdx.x;
    const int lane = tid & 31;
    const int wid  = tid >> 5;
    const int qi   = (TT/128 - 1) - (blockIdx.x / (BB*HH));
    const int bh   = blockIdx.x % (BB*HH);
    const int q0   = qi * 128;
    const int grp  = lane >> 2, qp = lane & 3;
    const int wr0  = q0 + wid * 16;

    const size_t bh_base = (size_t)bh * TT * HS;

    // Build Q fragments once -> per-warp SMEM
    {
#pragma unroll
        for (int ks = 0; ks < 4; ks++) {
            const int c0 = ks * 16 + qp * 2;
            const size_t r0 = bh_base + (size_t)(wr0 + grp) * HS;
            const size_t r1 = r0 + 8 * HS;
            uint32_t* q0p = &qsm[((wid * 4 + ks) * 4) * 32 + lane];
            q0p[0*32] = *(const uint32_t*)&g_Q16[r0 + c0];
            q0p[1*32] = *(const uint32_t*)&g_Q16[r1 + c0];
            q0p[2*32] = *(const uint32_t*)&g_Q16[r0 + c0 + 8];
            q0p[3*32] = *(const uint32_t*)&g_Q16[r1 + c0 + 8];
        }
    }

    float oacc[8][4];
    float mi[2] = {-1e30f, -1e30f}, li[2] = {0.f, 0.f};
#pragma unroll
    for (int j = 0; j < 8; j++)
#pragma unroll
        for (int c = 0; c < 4; c++) oacc[j][c] = 0.f;

    const int k4row = ((lane >> 4) & 1) * 8 + (lane & 7);
    const int k4col = ((lane >> 3) & 1) * 8;
    const int v4row = ((lane >> 3) & 1) * 8 + (lane & 7);
    const int v4col = ((lane >> 4) & 1) * 8;

    auto fillkv = [&](int buf, int k0) {
        const uint32_t d0 = sm_base + buf * A_STAGE * 2;
        const size_t gb = bh_base + (size_t)k0 * HS;
#pragma unroll
        for (int u = 0; u < 4; u++) {
            const int idx = tid + u * 256;      // 0..1023
            const int arr = idx >> 9;           // 0 = K, 1 = V
            const int w   = idx & 511;
            const int r   = w >> 3;
            const int c8  = (w & 7) * 8;
            const __half* src = (arr == 0)
                ? g_K16 + gb + (size_t)r * HS + c8
                : g_V16 + gb + (size_t)r * HS + c8;
            cp16(d0 + (arr * A_ARR + r * APAD + c8) * 2, src);
        }
        CP_COMMIT();
    };

    const int niters = 2 * qi + 2;
    fillkv(0, 0);
    for (int kj = 0; kj < niters; kj++) {
        const int k0 = kj * 64;
        const int buf = kj & 1;
        if (kj + 1 < niters) { fillkv(buf ^ 1, (kj + 1) * 64); CP_WAIT1(); }
        else                   CP_WAIT0();
        __syncthreads();

        if (k0 <= wr0 + 15) {
            const uint32_t sK = sm_base + (buf * A_STAGE) * 2;
            const uint32_t sV = sK + A_ARR * 2;

            // S = q * k (single pass fp16)
            float sacc[8][4];
#pragma unroll
            for (int j = 0; j < 8; j++)
#pragma unroll
                for (int c = 0; c < 4; c++) sacc[j][c] = 0.f;

#pragma unroll
            for (int ks = 0; ks < 4; ks++) {
                uint32_t qf[4];
                const uint32_t* qp0 = &qsm[((wid * 4 + ks) * 4) * 32 + lane];
#pragma unroll
                for (int r = 0; r < 4; r++) qf[r] = qp0[r*32];
#pragma unroll
                for (int jp = 0; jp < 4; jp++) {
                    uint32_t kb[4];
                    const int off = ((jp * 16 + k4row) * APAD + ks * 16 + k4col) * 2;
                    ldsm_x4(kb, sK + off);
                    mma16816h(sacc[2*jp],   qf, kb[0], kb[1]);
                    mma16816h(sacc[2*jp+1], qf, kb[2], kb[3]);
                }
            }

            // Causal mask (partially-masked tiles only)
            if (k0 + 63 > wr0) {
#pragma unroll
                for (int j = 0; j < 8; j++) {
#pragma unroll
                    for (int c = 0; c < 4; c++) {
                        const int col = k0 + j * 8 + qp * 2 + (c & 1);
                        const int row = wr0 + grp + ((c >> 1) * 8);
                        if (col > row) sacc[j][c] = -1e30f;
                    }
                }
            }

            // Online softmax
#pragma unroll
            for (int rr = 0; rr < 2; rr++) {
                float mx = -1e30f;
#pragma unroll
                for (int j = 0; j < 8; j++) {
                    mx = fmaxf(mx, sacc[j][rr * 2]);
                    mx = fmaxf(mx, sacc[j][rr * 2 + 1]);
                }
                mx = fmaxf(mx, __shfl_xor_sync(0xffffffffu, mx, 1));
                mx = fmaxf(mx, __shfl_xor_sync(0xffffffffu, mx, 2));
                const float mnew = fmaxf(mi[rr], mx);
                const float corr = __expf(mi[rr] - mnew);
                float sum = 0.f;
#pragma unroll
                for (int j = 0; j < 8; j++) {
                    float p0 = __expf(sacc[j][rr * 2]     - mnew);
                    float p1 = __expf(sacc[j][rr * 2 + 1] - mnew);
                    sacc[j][rr * 2] = p0; sacc[j][rr * 2 + 1] = p1;
                    sum += p0 + p1;
                }
                sum += __shfl_xor_sync(0xffffffffu, sum, 1);
                sum += __shfl_xor_sync(0xffffffffu, sum, 2);
                li[rr] = li[rr] * corr + sum;
                mi[rr] = mnew;
#pragma unroll
                for (int j = 0; j < 8; j++) {
                    oacc[j][rr * 2]     *= corr;
                    oacc[j][rr * 2 + 1] *= corr;
                }
            }

            // P fragments (fp16)
            uint32_t ph[4][4];
#pragma unroll
            for (int ks = 0; ks < 4; ks++) {
                const int j0 = 2 * ks, j1 = 2 * ks + 1;
                ph[ks][0] = pack_h2(sacc[j0][0], sacc[j0][1]);
                ph[ks][1] = pack_h2(sacc[j0][2], sacc[j0][3]);
                ph[ks][2] = pack_h2(sacc[j1][0], sacc[j1][1]);
                ph[ks][3] = pack_h2(sacc[j1][2], sacc[j1][3]);
            }

            // O += p * v (single pass fp16)
#pragma unroll
            for (int ks = 0; ks < 4; ks++) {
#pragma unroll
                for (int jop = 0; jop < 4; jop++) {
                    uint32_t vb[4];
                    const int off = ((ks * 16 + v4row) * APAD + (2*jop) * 8 + v4col) * 2;
                    ldsm_x4t(vb, sV + off);
                    mma16816h(oacc[2*jop],   ph[ks], vb[0], vb[1]);
                    mma16816h(oacc[2*jop+1], ph[ks], vb[2], vb[3]);
                }
            }
        }
        __syncthreads();
    }

    // Epilogue: write fp16 O (feeds fp16 projection GEMM)
    const int b = bh / HH, h = bh % HH;
#pragma unroll
    for (int rr = 0; rr < 2; rr++) {
        const int t = wr0 + grp + rr * 8;
        const float inv = 1.f / li[rr];
        const size_t base = (size_t)(b * TT + t) * CC + h * HS;
#pragma unroll
        for (int jo = 0; jo < 8; jo++) {
            *(uint32_t*)&g_a16[base + jo * 8 + qp * 2] =
                pack_h2(oacc[jo][rr * 2] * inv, oacc[jo][rr * 2 + 1] * inv);
        }
    }
}

// ---------------------------------------------------------------------------
extern "C" void kernel_launch(void* const* d_in, const int* in_sizes, int n_in,
                              void* d_out, int out_size)
{
    const float* x      = (const float*)d_in[0];
    const float* w_attn = (const float*)d_in[1];
    const float* b_attn = (const float*)d_in[2];
    const float* w_proj = (const float*)d_in[3];
    const float* b_proj = (const float*)d_in[4];
    float* out = (float*)d_out;
    (void)in_sizes; (void)n_in; (void)out_size;

    __half *x16, *wa16, *wp16, *a16;
    cudaGetSymbolAddress((void**)&x16,  g_x16);
    cudaGetSymbolAddress((void**)&wa16, g_wa16);
    cudaGetSymbolAddress((void**)&wp16, g_wp16);
    cudaGetSymbolAddress((void**)&a16,  g_a16);

    cudaFuncSetAttribute(mma_gemm<0>, cudaFuncAttributeMaxDynamicSharedMemorySize, GEMM_SMEM);
    cudaFuncSetAttribute(mma_gemm<1>, cudaFuncAttributeMaxDynamicSharedMemorySize, GEMM_SMEM);
    cudaFuncSetAttribute(attn_mma,    cudaFuncAttributeMaxDynamicSharedMemorySize, ATTN_SMEM);

    // 0) convert inputs to fp16
    conv16_kernel<<<(MM*CC/4 + 255)/256, 256>>>(x, x16, MM*CC);
    conv16_kernel<<<(3*CC*CC/4 + 255)/256, 256>>>(w_attn, wa16, 3*CC*CC);
    conv16_kernel<<<(CC*CC/4 + 255)/256, 256>>>(w_proj, wp16, CC*CC);

    // 1) QKV projection (fp16) -> Q16 scaled, K16, V16
    mma_gemm<0><<<dim3(3*CC/128, MM/128), 256, GEMM_SMEM>>>(x16, wa16, b_attn, nullptr, 3*CC);

    // 2) Flash attention (fp16 single-pass, LPT)
    attn_mma<<<(TT/128) * BB * HH, 256, ATTN_SMEM>>>();

    // 3) Output projection (fp16)
    mma_gemm<1><<<dim3(CC/128, MM/128), 256, GEMM_SMEM>>>(a16, wp16, b_proj, out, CC);
}